// round 9
// baseline (speedup 1.0000x reference)
#include <cuda_runtime.h>
#include <cuda_bf16.h>
#include <cstdint>

// orig_fea [256, 300, 256] f32; ind0/ind1 [32,32,4] i32; W1a/W1b [256,256];
// b1[256]; W2[256,1]; b2[1]. L=128, pool=1200.
#define LN   128
#define DD   256
#define HH   256
#define NUMG 32
#define BAG  300

// Scratch: h0/h1 transposed: [side][n][h][a]  (8 MB)
__device__ float g_hT[2][NUMG][HH][LN];

// ============================ helpers ============================
__device__ __forceinline__ uint32_t smem_u32(const void* p) {
    uint32_t a;
    asm("{ .reg .u64 t; cvta.to.shared.u64 t, %1; cvt.u32.u64 %0, t; }"
        : "=r"(a) : "l"(p));
    return a;
}
// f32 pair -> bf16x2 (low half = x0); also return rounded values as f32
__device__ __forceinline__ uint32_t cvt_pair(float x0, float x1, float& h0f, float& h1f) {
    uint32_t r;
    asm("cvt.rn.bf16x2.f32 %0, %1, %2;" : "=r"(r) : "f"(x1), "f"(x0));
    h0f = __uint_as_float(r << 16);
    h1f = __uint_as_float(r & 0xFFFF0000u);
    return r;
}
__device__ __forceinline__ uint32_t cvt_pair_n(float x0, float x1) {
    uint32_t r;
    asm("cvt.rn.bf16x2.f32 %0, %1, %2;" : "=r"(r) : "f"(x1), "f"(x0));
    return r;
}
__device__ __forceinline__ void ldsm4(uint32_t* r, uint32_t addr) {
    asm volatile("ldmatrix.sync.aligned.m8n8.x4.shared.b16 {%0,%1,%2,%3}, [%4];"
        : "=r"(r[0]), "=r"(r[1]), "=r"(r[2]), "=r"(r[3]) : "r"(addr));
}
__device__ __forceinline__ void ldsm4t(uint32_t* r, uint32_t addr) {
    asm volatile("ldmatrix.sync.aligned.m8n8.x4.trans.shared.b16 {%0,%1,%2,%3}, [%4];"
        : "=r"(r[0]), "=r"(r[1]), "=r"(r[2]), "=r"(r[3]) : "r"(addr));
}
__device__ __forceinline__ void mma16816(float* d, const uint32_t* a,
                                         uint32_t b0, uint32_t b1) {
    asm volatile("mma.sync.aligned.m16n8k16.row.col.f32.bf16.bf16.f32 "
        "{%0,%1,%2,%3}, {%4,%5,%6,%7}, {%8,%9}, {%0,%1,%2,%3};"
        : "+f"(d[0]), "+f"(d[1]), "+f"(d[2]), "+f"(d[3])
        : "r"(a[0]), "r"(a[1]), "r"(a[2]), "r"(a[3]), "r"(b0), "r"(b1));
}
// XOR swizzle: rows of 128B, 16B atoms permuted by row%8 -> conflict-free LDSM
#define SWZ(row, kb) ((row) * 128 + ((kb) ^ (((row) & 7) << 4)))

// ---------------------------------------------------------------------------
// Kernel 1: mma.sync bf16 split-precision GEMM (UNCHANGED from R8, 21us).
// ---------------------------------------------------------------------------
__global__ __launch_bounds__(256)
void gemm_mma_kernel(const float* __restrict__ orig,
                     const int*   __restrict__ ind0,
                     const int*   __restrict__ ind1,
                     const float* __restrict__ W1a,
                     const float* __restrict__ W1b,
                     const float* __restrict__ bias1)
{
    extern __shared__ char dsm[];
    __shared__ int rowoff[128];

    const int t = threadIdx.x, l = t & 31, w = t >> 5;
    const int b    = blockIdx.x;
    const int side = b >> 7;
    const int n    = (b >> 2) & 31;
    const int h0   = (b & 3) * 64;
    const int m0   = (w & 3) * 32;
    const int n0   = (w >> 2) * 32;
    const float* __restrict__ Wmat = side ? W1b : W1a;

    const uint32_t smb = smem_u32(dsm);
    const int offAhi = 0, offAlo = 16384, offBhi = 32768, offBlo = 40960;

    if (t < 128) {
        const int* __restrict__ ind = side ? ind1 : ind0;
        int p = ind[n * LN + t] + BAG * (t & 3);
        rowoff[t] = ((n * 2 + side) * 1200 + p) * DD;
    }
    __syncthreads();

    const int arow  = t >> 1;
    const int halfk = t & 1;
    const int ro    = rowoff[arow];
    const int bkr   = t >> 2;
    const int bhq   = t & 3;

    float acc[2][4][4];
#pragma unroll
    for (int mt = 0; mt < 2; mt++)
#pragma unroll
        for (int nt = 0; nt < 4; nt++)
#pragma unroll
            for (int i = 0; i < 4; i++) acc[mt][nt][i] = 0.f;

#pragma unroll 1
    for (int c = 0; c < 4; c++) {
        {
            const float4* ap = (const float4*)(orig + ro + c * 64 + halfk * 32);
            float4 av[8];
#pragma unroll
            for (int q = 0; q < 8; q++) av[q] = ap[q];
#pragma unroll
            for (int q2 = 0; q2 < 4; q2++) {
                float4 u = av[2 * q2], v = av[2 * q2 + 1];
                float r0, r1, r2, r3, r4, r5, r6, r7;
                uint32_t hp0 = cvt_pair(u.x, u.y, r0, r1);
                uint32_t hp1 = cvt_pair(u.z, u.w, r2, r3);
                uint32_t hp2 = cvt_pair(v.x, v.y, r4, r5);
                uint32_t hp3 = cvt_pair(v.z, v.w, r6, r7);
                uint32_t lp0 = cvt_pair_n(u.x - r0, u.y - r1);
                uint32_t lp1 = cvt_pair_n(u.z - r2, u.w - r3);
                uint32_t lp2 = cvt_pair_n(v.x - r4, v.y - r5);
                uint32_t lp3 = cvt_pair_n(v.z - r6, v.w - r7);
                int kb = halfk * 64 + q2 * 16;
                *(uint4*)(dsm + offAhi + SWZ(arow, kb)) = make_uint4(hp0, hp1, hp2, hp3);
                *(uint4*)(dsm + offAlo + SWZ(arow, kb)) = make_uint4(lp0, lp1, lp2, lp3);
            }
        }
        {
            const float4* wp = (const float4*)&Wmat[(c * 64 + bkr) * HH + h0 + bhq * 16];
            float4 wv[4];
#pragma unroll
            for (int q = 0; q < 4; q++) wv[q] = wp[q];
            uint32_t hi[8], lo[8];
#pragma unroll
            for (int q2 = 0; q2 < 2; q2++) {
                float4 u = wv[2 * q2], v = wv[2 * q2 + 1];
                float r0, r1, r2, r3, r4, r5, r6, r7;
                hi[q2 * 4 + 0] = cvt_pair(u.x, u.y, r0, r1);
                hi[q2 * 4 + 1] = cvt_pair(u.z, u.w, r2, r3);
                hi[q2 * 4 + 2] = cvt_pair(v.x, v.y, r4, r5);
                hi[q2 * 4 + 3] = cvt_pair(v.z, v.w, r6, r7);
                lo[q2 * 4 + 0] = cvt_pair_n(u.x - r0, u.y - r1);
                lo[q2 * 4 + 1] = cvt_pair_n(u.z - r2, u.w - r3);
                lo[q2 * 4 + 2] = cvt_pair_n(v.x - r4, v.y - r5);
                lo[q2 * 4 + 3] = cvt_pair_n(v.z - r6, v.w - r7);
            }
            int kb = bhq * 32;
            *(uint4*)(dsm + offBhi + SWZ(bkr, kb))      = make_uint4(hi[0], hi[1], hi[2], hi[3]);
            *(uint4*)(dsm + offBhi + SWZ(bkr, kb + 16)) = make_uint4(hi[4], hi[5], hi[6], hi[7]);
            *(uint4*)(dsm + offBlo + SWZ(bkr, kb))      = make_uint4(lo[0], lo[1], lo[2], lo[3]);
            *(uint4*)(dsm + offBlo + SWZ(bkr, kb + 16)) = make_uint4(lo[4], lo[5], lo[6], lo[7]);
        }
        __syncthreads();

#pragma unroll
        for (int ks = 0; ks < 4; ks++) {
            const int rA  = m0 + (l & 15);
            const int kbL = ks * 32 + ((l >> 4) << 4);
            uint32_t ahi[2][4], alo[2][4], bhi[2][4], blo[2][4];
            ldsm4(ahi[0], smb + offAhi + SWZ(rA, kbL));
            ldsm4(ahi[1], smb + offAhi + SWZ(rA + 16, kbL));
            ldsm4(alo[0], smb + offAlo + SWZ(rA, kbL));
            ldsm4(alo[1], smb + offAlo + SWZ(rA + 16, kbL));
            const int rK = ks * 16 + (l & 15);
            const int hb = ((l >> 4) << 4);
            ldsm4t(bhi[0], smb + offBhi + SWZ(rK, n0 * 2 + hb));
            ldsm4t(bhi[1], smb + offBhi + SWZ(rK, n0 * 2 + 32 + hb));
            ldsm4t(blo[0], smb + offBlo + SWZ(rK, n0 * 2 + hb));
            ldsm4t(blo[1], smb + offBlo + SWZ(rK, n0 * 2 + 32 + hb));
#pragma unroll
            for (int mt = 0; mt < 2; mt++)
#pragma unroll
                for (int g = 0; g < 2; g++)
#pragma unroll
                    for (int s = 0; s < 2; s++) {
                        int nt = g * 2 + s;
                        mma16816(acc[mt][nt], ahi[mt], bhi[g][2 * s], bhi[g][2 * s + 1]);
                        mma16816(acc[mt][nt], alo[mt], bhi[g][2 * s], bhi[g][2 * s + 1]);
                        mma16816(acc[mt][nt], ahi[mt], blo[g][2 * s], blo[g][2 * s + 1]);
                    }
        }
        __syncthreads();
    }

    const int g    = l >> 2;
    const int tid4 = l & 3;
#pragma unroll
    for (int mt = 0; mt < 2; mt++) {
        int ag = m0 + mt * 16 + g;
#pragma unroll
        for (int nt = 0; nt < 4; nt++) {
            int hg = h0 + n0 + nt * 8 + tid4 * 2;
            float bv0 = 0.f, bv1 = 0.f;
            if (side == 0) { bv0 = __ldg(&bias1[hg]); bv1 = __ldg(&bias1[hg + 1]); }
            g_hT[side][n][hg    ][ag    ] = acc[mt][nt][0] + bv0;
            g_hT[side][n][hg + 1][ag    ] = acc[mt][nt][1] + bv1;
            g_hT[side][n][hg    ][ag + 8] = acc[mt][nt][2] + bv0;
            g_hT[side][n][hg + 1][ag + 8] = acc[mt][nt][3] + bv1;
        }
    }
}

// ---------------------------------------------------------------------------
// Kernel 2 (REWORKED): barrier-free main loop. y rows read straight from L2
// via coalesced LDG.128 (8-deep MLP from unroll); xs + W2 staged to smem once.
// grid 512 = n(32) x a-tile(8, 16 a) x b-tile(2, 64 b); block 256:
//   tx = t&15 (patch col), ty = (t>>4)&3 (patch row), th = t>>6 (h mod 4).
// ---------------------------------------------------------------------------
__global__ __launch_bounds__(256)
void pairwise_kernel(const float* __restrict__ W2,
                     const float* __restrict__ b2,
                     float* __restrict__ out,
                     int write_pairs)
{
    const int bid = blockIdx.x;
    const int n   = bid >> 4;
    const int at  = (bid >> 1) & 7;
    const int bt  = bid & 1;
    const int a0  = at * 16;
    const int b0  = bt * 64;
    const int t   = threadIdx.x;
    const int tx  = t & 15;
    const int ty  = (t >> 4) & 3;
    const int th  = t >> 6;

    __shared__ float4 xs4[256][4];        // [h][a-quad]  16KB
    __shared__ float  ws[256];            // W2            1KB
    __shared__ float  red[3 * 64 * 16];   // reduction    12KB

    // stage xs (all 256 h, 16 a) + W2, one barrier total
#pragma unroll
    for (int r = 0; r < 4; r++) {
        int id = t + 256 * r;
        int hh = id >> 2, q = id & 3;
        xs4[hh][q] = *(const float4*)&g_hT[0][n][hh][a0 + q * 4];
    }
    ws[t] = W2[t];
    __syncthreads();

    float acc[4][4];
#pragma unroll
    for (int j = 0; j < 4; j++)
#pragma unroll
        for (int i = 0; i < 4; i++) acc[j][i] = 0.f;

    // y base: g_hT[1][n][hs][b0 + tx*4], advance by hs rows (LN/4 float4s)
    const float4* __restrict__ ybase =
        (const float4*)&g_hT[1][n][0][b0 + tx * 4];

#pragma unroll 8
    for (int u = 0; u < 64; u++) {
        const int hs = th + u * 4;
        float  wv = ws[hs];
        float4 x4 = xs4[hs][ty];
        float4 y4 = ybase[hs * (LN / 4)];
        float xa[4] = {x4.x, x4.y, x4.z, x4.w};
        float yb[4] = {y4.x, y4.y, y4.z, y4.w};
#pragma unroll
        for (int j = 0; j < 4; j++)
#pragma unroll
            for (int i = 0; i < 4; i++)
                acc[j][i] = fmaf(fmaxf(xa[j] + yb[i], 0.f), wv, acc[j][i]);
    }

    // 4-way h-split reduction via smem
    const int p = ty * 16 + tx;   // 0..63
    __syncthreads();
    if (th > 0) {
        int base = ((th - 1) * 64 + p) * 16;
#pragma unroll
        for (int j = 0; j < 4; j++)
#pragma unroll
            for (int i = 0; i < 4; i++) {
                int idx = j * 4 + i;
                red[base + ((idx + p) & 15)] = acc[j][i];
            }
    }
    __syncthreads();
    if (th == 0) {
        float s = 0.f;
#pragma unroll
        for (int j = 0; j < 4; j++)
#pragma unroll
            for (int i = 0; i < 4; i++) s += acc[j][i];
#pragma unroll
        for (int g = 0; g < 3; g++) {
            int base = (g * 64 + p) * 16;
#pragma unroll
            for (int idx = 0; idx < 16; idx++)
                s += red[base + ((idx + p) & 15)];
        }
        s += 16.f * __ldg(b2);
        const int m = at * 4 + ty;
        const int lcol = bt * 16 + tx;
        out[n * 1024 + m * 32 + lcol] = s;
    }

    if (write_pairs && t < 128) {
        int id    = bid * 128 + t;   // 0..65535
        int pi    = id >> 1;
        int which = id & 1;
        int idx   = pi & 1023;
        int v = which ? (idx & 31) : (idx >> 5);
        out[NUMG * 1024 + id] = (float)v;
    }
}

extern "C" void kernel_launch(void* const* d_in, const int* in_sizes, int n_in,
                              void* d_out, int out_size)
{
    const float* orig = (const float*)d_in[0];
    const int*   ind0 = (const int*)d_in[1];
    const int*   ind1 = (const int*)d_in[2];
    int i = 3;
    if (n_in >= 9 && in_sizes[3] == 1) i = 4;   // scalar k materialized
    const float* W1a = (const float*)d_in[i + 0];
    const float* W1b = (const float*)d_in[i + 1];
    const float* b1  = (const float*)d_in[i + 2];
    const float* W2  = (const float*)d_in[i + 3];
    const float* b2  = (const float*)d_in[i + 4];
    float* out = (float*)d_out;

    const int scores_elems = NUMG * 1024;
    const int pairs_elems  = NUMG * 1024 * 2;
    int write_pairs = (out_size >= scores_elems + pairs_elems) ? 1 : 0;

    const int DSM = 49152;   // Ahi/Alo 16KB + Bhi/Blo 8KB each
    cudaFuncSetAttribute(gemm_mma_kernel,
                         cudaFuncAttributeMaxDynamicSharedMemorySize, DSM);

    gemm_mma_kernel<<<256, 256, DSM>>>(orig, ind0, ind1, W1a, W1b, b1);
    pairwise_kernel<<<512, 256>>>(W2, b2, out, write_pairs);
}

// round 10
// speedup vs baseline: 1.0928x; 1.0928x over previous
#include <cuda_runtime.h>
#include <cuda_bf16.h>
#include <cstdint>

// orig_fea [256, 300, 256] f32; ind0/ind1 [32,32,4] i32; W1a/W1b [256,256];
// b1[256]; W2[256,1]; b2[1]. L=128, pool=1200.
#define LN   128
#define DD   256
#define HH   256
#define NUMG 32
#define BAG  300

// Scratch: h0/h1 transposed: [side][n][h][a]  (8 MB)
__device__ float g_hT[2][NUMG][HH][LN];

// ============================ helpers ============================
__device__ __forceinline__ uint32_t smem_u32(const void* p) {
    uint32_t a;
    asm("{ .reg .u64 t; cvta.to.shared.u64 t, %1; cvt.u32.u64 %0, t; }"
        : "=r"(a) : "l"(p));
    return a;
}
// f32 pair -> bf16x2 (low half = x0); also return rounded values as f32
__device__ __forceinline__ uint32_t cvt_pair(float x0, float x1, float& h0f, float& h1f) {
    uint32_t r;
    asm("cvt.rn.bf16x2.f32 %0, %1, %2;" : "=r"(r) : "f"(x1), "f"(x0));
    h0f = __uint_as_float(r << 16);
    h1f = __uint_as_float(r & 0xFFFF0000u);
    return r;
}
__device__ __forceinline__ uint32_t cvt_pair_n(float x0, float x1) {
    uint32_t r;
    asm("cvt.rn.bf16x2.f32 %0, %1, %2;" : "=r"(r) : "f"(x1), "f"(x0));
    return r;
}
__device__ __forceinline__ void ldsm4(uint32_t* r, uint32_t addr) {
    asm volatile("ldmatrix.sync.aligned.m8n8.x4.shared.b16 {%0,%1,%2,%3}, [%4];"
        : "=r"(r[0]), "=r"(r[1]), "=r"(r[2]), "=r"(r[3]) : "r"(addr));
}
__device__ __forceinline__ void ldsm4t(uint32_t* r, uint32_t addr) {
    asm volatile("ldmatrix.sync.aligned.m8n8.x4.trans.shared.b16 {%0,%1,%2,%3}, [%4];"
        : "=r"(r[0]), "=r"(r[1]), "=r"(r[2]), "=r"(r[3]) : "r"(addr));
}
__device__ __forceinline__ void mma16816(float* d, const uint32_t* a,
                                         uint32_t b0, uint32_t b1) {
    asm volatile("mma.sync.aligned.m16n8k16.row.col.f32.bf16.bf16.f32 "
        "{%0,%1,%2,%3}, {%4,%5,%6,%7}, {%8,%9}, {%0,%1,%2,%3};"
        : "+f"(d[0]), "+f"(d[1]), "+f"(d[2]), "+f"(d[3])
        : "r"(a[0]), "r"(a[1]), "r"(a[2]), "r"(a[3]), "r"(b0), "r"(b1));
}
// XOR swizzle: rows of 128B, 16B atoms permuted by row%8 -> conflict-free LDSM
#define SWZ(row, kb) ((row) * 128 + ((kb) ^ (((row) & 7) << 4)))

// ---------------------------------------------------------------------------
// Kernel 1: mma.sync bf16 split-precision GEMM (UNCHANGED from R8).
// ---------------------------------------------------------------------------
__global__ __launch_bounds__(256)
void gemm_mma_kernel(const float* __restrict__ orig,
                     const int*   __restrict__ ind0,
                     const int*   __restrict__ ind1,
                     const float* __restrict__ W1a,
                     const float* __restrict__ W1b,
                     const float* __restrict__ bias1)
{
    extern __shared__ char dsm[];
    __shared__ int rowoff[128];

    const int t = threadIdx.x, l = t & 31, w = t >> 5;
    const int b    = blockIdx.x;
    const int side = b >> 7;
    const int n    = (b >> 2) & 31;
    const int h0   = (b & 3) * 64;
    const int m0   = (w & 3) * 32;
    const int n0   = (w >> 2) * 32;
    const float* __restrict__ Wmat = side ? W1b : W1a;

    const uint32_t smb = smem_u32(dsm);
    const int offAhi = 0, offAlo = 16384, offBhi = 32768, offBlo = 40960;

    if (t < 128) {
        const int* __restrict__ ind = side ? ind1 : ind0;
        int p = ind[n * LN + t] + BAG * (t & 3);
        rowoff[t] = ((n * 2 + side) * 1200 + p) * DD;
    }
    __syncthreads();

    const int arow  = t >> 1;
    const int halfk = t & 1;
    const int ro    = rowoff[arow];
    const int bkr   = t >> 2;
    const int bhq   = t & 3;

    float acc[2][4][4];
#pragma unroll
    for (int mt = 0; mt < 2; mt++)
#pragma unroll
        for (int nt = 0; nt < 4; nt++)
#pragma unroll
            for (int i = 0; i < 4; i++) acc[mt][nt][i] = 0.f;

#pragma unroll 1
    for (int c = 0; c < 4; c++) {
        {
            const float4* ap = (const float4*)(orig + ro + c * 64 + halfk * 32);
            float4 av[8];
#pragma unroll
            for (int q = 0; q < 8; q++) av[q] = ap[q];
#pragma unroll
            for (int q2 = 0; q2 < 4; q2++) {
                float4 u = av[2 * q2], v = av[2 * q2 + 1];
                float r0, r1, r2, r3, r4, r5, r6, r7;
                uint32_t hp0 = cvt_pair(u.x, u.y, r0, r1);
                uint32_t hp1 = cvt_pair(u.z, u.w, r2, r3);
                uint32_t hp2 = cvt_pair(v.x, v.y, r4, r5);
                uint32_t hp3 = cvt_pair(v.z, v.w, r6, r7);
                uint32_t lp0 = cvt_pair_n(u.x - r0, u.y - r1);
                uint32_t lp1 = cvt_pair_n(u.z - r2, u.w - r3);
                uint32_t lp2 = cvt_pair_n(v.x - r4, v.y - r5);
                uint32_t lp3 = cvt_pair_n(v.z - r6, v.w - r7);
                int kb = halfk * 64 + q2 * 16;
                *(uint4*)(dsm + offAhi + SWZ(arow, kb)) = make_uint4(hp0, hp1, hp2, hp3);
                *(uint4*)(dsm + offAlo + SWZ(arow, kb)) = make_uint4(lp0, lp1, lp2, lp3);
            }
        }
        {
            const float4* wp = (const float4*)&Wmat[(c * 64 + bkr) * HH + h0 + bhq * 16];
            float4 wv[4];
#pragma unroll
            for (int q = 0; q < 4; q++) wv[q] = wp[q];
            uint32_t hi[8], lo[8];
#pragma unroll
            for (int q2 = 0; q2 < 2; q2++) {
                float4 u = wv[2 * q2], v = wv[2 * q2 + 1];
                float r0, r1, r2, r3, r4, r5, r6, r7;
                hi[q2 * 4 + 0] = cvt_pair(u.x, u.y, r0, r1);
                hi[q2 * 4 + 1] = cvt_pair(u.z, u.w, r2, r3);
                hi[q2 * 4 + 2] = cvt_pair(v.x, v.y, r4, r5);
                hi[q2 * 4 + 3] = cvt_pair(v.z, v.w, r6, r7);
                lo[q2 * 4 + 0] = cvt_pair_n(u.x - r0, u.y - r1);
                lo[q2 * 4 + 1] = cvt_pair_n(u.z - r2, u.w - r3);
                lo[q2 * 4 + 2] = cvt_pair_n(v.x - r4, v.y - r5);
                lo[q2 * 4 + 3] = cvt_pair_n(v.z - r6, v.w - r7);
            }
            int kb = bhq * 32;
            *(uint4*)(dsm + offBhi + SWZ(bkr, kb))      = make_uint4(hi[0], hi[1], hi[2], hi[3]);
            *(uint4*)(dsm + offBhi + SWZ(bkr, kb + 16)) = make_uint4(hi[4], hi[5], hi[6], hi[7]);
            *(uint4*)(dsm + offBlo + SWZ(bkr, kb))      = make_uint4(lo[0], lo[1], lo[2], lo[3]);
            *(uint4*)(dsm + offBlo + SWZ(bkr, kb + 16)) = make_uint4(lo[4], lo[5], lo[6], lo[7]);
        }
        __syncthreads();

#pragma unroll
        for (int ks = 0; ks < 4; ks++) {
            const int rA  = m0 + (l & 15);
            const int kbL = ks * 32 + ((l >> 4) << 4);
            uint32_t ahi[2][4], alo[2][4], bhi[2][4], blo[2][4];
            ldsm4(ahi[0], smb + offAhi + SWZ(rA, kbL));
            ldsm4(ahi[1], smb + offAhi + SWZ(rA + 16, kbL));
            ldsm4(alo[0], smb + offAlo + SWZ(rA, kbL));
            ldsm4(alo[1], smb + offAlo + SWZ(rA + 16, kbL));
            const int rK = ks * 16 + (l & 15);
            const int hb = ((l >> 4) << 4);
            ldsm4t(bhi[0], smb + offBhi + SWZ(rK, n0 * 2 + hb));
            ldsm4t(bhi[1], smb + offBhi + SWZ(rK, n0 * 2 + 32 + hb));
            ldsm4t(blo[0], smb + offBlo + SWZ(rK, n0 * 2 + hb));
            ldsm4t(blo[1], smb + offBlo + SWZ(rK, n0 * 2 + 32 + hb));
#pragma unroll
            for (int mt = 0; mt < 2; mt++)
#pragma unroll
                for (int g = 0; g < 2; g++)
#pragma unroll
                    for (int s = 0; s < 2; s++) {
                        int nt = g * 2 + s;
                        mma16816(acc[mt][nt], ahi[mt], bhi[g][2 * s], bhi[g][2 * s + 1]);
                        mma16816(acc[mt][nt], alo[mt], bhi[g][2 * s], bhi[g][2 * s + 1]);
                        mma16816(acc[mt][nt], ahi[mt], blo[g][2 * s], blo[g][2 * s + 1]);
                    }
        }
        __syncthreads();
    }

    const int g    = l >> 2;
    const int tid4 = l & 3;
#pragma unroll
    for (int mt = 0; mt < 2; mt++) {
        int ag = m0 + mt * 16 + g;
#pragma unroll
        for (int nt = 0; nt < 4; nt++) {
            int hg = h0 + n0 + nt * 8 + tid4 * 2;
            float bv0 = 0.f, bv1 = 0.f;
            if (side == 0) { bv0 = __ldg(&bias1[hg]); bv1 = __ldg(&bias1[hg + 1]); }
            g_hT[side][n][hg    ][ag    ] = acc[mt][nt][0] + bv0;
            g_hT[side][n][hg + 1][ag    ] = acc[mt][nt][1] + bv1;
            g_hT[side][n][hg    ][ag + 8] = acc[mt][nt][2] + bv0;
            g_hT[side][n][hg + 1][ag + 8] = acc[mt][nt][3] + bv1;
        }
    }
}

// ---------------------------------------------------------------------------
// Kernel 2: R8 smem-staged structure; relu moved OFF the alu pipe via the
// bit-exact identity relu(s)*w == (s + |s|) * (0.5*w)  (FADD with |.| source
// modifier -> fma pipe). W2 pre-halved in smem (no per-iter LDG).
// grid 512 = n(32) x a-tile(8, 16 a) x b-tile(2, 64 b); block 256:
//   tx = t&15 (patch col), ty = (t>>4)&3 (patch row), th = t>>6 (h mod 4).
// ---------------------------------------------------------------------------
__global__ __launch_bounds__(256)
void pairwise_kernel(const float* __restrict__ W2,
                     const float* __restrict__ b2,
                     float* __restrict__ out,
                     int write_pairs)
{
    const int bid = blockIdx.x;
    const int n   = bid >> 4;
    const int at  = (bid >> 1) & 7;
    const int bt  = bid & 1;
    const int a0  = at * 16;
    const int b0  = bt * 64;
    const int t   = threadIdx.x;
    const int tx  = t & 15;
    const int ty  = (t >> 4) & 3;
    const int th  = t >> 6;

    __shared__ float4 xs4[256][4];       // [h][a-quad]  16KB
    __shared__ float4 ys4[2][32][16];    // [buf][h][b-quad]  16KB
    __shared__ float  ws[256];           // 0.5 * W2      1KB

#pragma unroll
    for (int r = 0; r < 4; r++) {
        int id = t + 256 * r;
        int hh = id >> 2, q = id & 3;
        xs4[hh][q] = *(const float4*)&g_hT[0][n][hh][a0 + q * 4];
    }
#pragma unroll
    for (int r = 0; r < 2; r++) {
        int id = t + 256 * r;
        int hh = id >> 4, q = id & 15;
        ys4[0][hh][q] = *(const float4*)&g_hT[1][n][hh][b0 + q * 4];
    }
    ws[t] = 0.5f * W2[t];
    __syncthreads();

    float acc[4][4];
#pragma unroll
    for (int j = 0; j < 4; j++)
#pragma unroll
        for (int i = 0; i < 4; i++) acc[j][i] = 0.f;

    int buf = 0;
#pragma unroll 1
    for (int hc = 0; hc < 8; hc++) {
        float4 st[2];
        if (hc < 7) {
#pragma unroll
            for (int r = 0; r < 2; r++) {
                int id = t + 256 * r;
                int hh = id >> 4, q = id & 15;
                st[r] = *(const float4*)&g_hT[1][n][(hc + 1) * 32 + hh][b0 + q * 4];
            }
        }
#pragma unroll
        for (int u = 0; u < 8; u++) {
            int hh = th + u * 4;
            int hs = hc * 32 + hh;
            float  wv = ws[hs];                 // pre-halved
            float4 x4 = xs4[hs][ty];
            float4 y4 = ys4[buf][hh][tx];
            float xa[4] = {x4.x, x4.y, x4.z, x4.w};
            float yb[4] = {y4.x, y4.y, y4.z, y4.w};
#pragma unroll
            for (int j = 0; j < 4; j++)
#pragma unroll
                for (int i = 0; i < 4; i++) {
                    float s = xa[j] + yb[i];
                    float uu = s + fabsf(s);     // FADD with |.| modifier
                    acc[j][i] = fmaf(uu, wv, acc[j][i]);
                }
        }
        if (hc < 7) {
            int nb = buf ^ 1;
#pragma unroll
            for (int r = 0; r < 2; r++) {
                int id = t + 256 * r;
                int hh = id >> 4, q = id & 15;
                ys4[nb][hh][q] = st[r];
            }
            __syncthreads();
            buf = nb;
        }
    }

    // 4-way reduction in dead xs region (16KB)
    float* red = (float*)&xs4[0][0];
    const int p = ty * 16 + tx;   // 0..63
    __syncthreads();
    if (th > 0) {
        int base = ((th - 1) * 64 + p) * 16;
#pragma unroll
        for (int j = 0; j < 4; j++)
#pragma unroll
            for (int i = 0; i < 4; i++) {
                int idx = j * 4 + i;
                red[base + ((idx + p) & 15)] = acc[j][i];
            }
    }
    __syncthreads();
    if (th == 0) {
        float s = 0.f;
#pragma unroll
        for (int j = 0; j < 4; j++)
#pragma unroll
            for (int i = 0; i < 4; i++) s += acc[j][i];
#pragma unroll
        for (int g = 0; g < 3; g++) {
            int base = (g * 64 + p) * 16;
#pragma unroll
            for (int idx = 0; idx < 16; idx++)
                s += red[base + ((idx + p) & 15)];
        }
        s += 16.f * __ldg(b2);
        const int m = at * 4 + ty;
        const int lcol = bt * 16 + tx;
        out[n * 1024 + m * 32 + lcol] = s;
    }

    if (write_pairs && t < 128) {
        int id    = bid * 128 + t;   // 0..65535
        int pi    = id >> 1;
        int which = id & 1;
        int idx   = pi & 1023;
        int v = which ? (idx & 31) : (idx >> 5);
        out[NUMG * 1024 + id] = (float)v;
    }
}

extern "C" void kernel_launch(void* const* d_in, const int* in_sizes, int n_in,
                              void* d_out, int out_size)
{
    const float* orig = (const float*)d_in[0];
    const int*   ind0 = (const int*)d_in[1];
    const int*   ind1 = (const int*)d_in[2];
    int i = 3;
    if (n_in >= 9 && in_sizes[3] == 1) i = 4;   // scalar k materialized
    const float* W1a = (const float*)d_in[i + 0];
    const float* W1b = (const float*)d_in[i + 1];
    const float* b1  = (const float*)d_in[i + 2];
    const float* W2  = (const float*)d_in[i + 3];
    const float* b2  = (const float*)d_in[i + 4];
    float* out = (float*)d_out;

    const int scores_elems = NUMG * 1024;
    const int pairs_elems  = NUMG * 1024 * 2;
    int write_pairs = (out_size >= scores_elems + pairs_elems) ? 1 : 0;

    const int DSM = 49152;   // Ahi/Alo 16KB + Bhi/Blo 8KB each
    cudaFuncSetAttribute(gemm_mma_kernel,
                         cudaFuncAttributeMaxDynamicSharedMemorySize, DSM);

    gemm_mma_kernel<<<256, 256, DSM>>>(orig, ind0, ind1, W1a, W1b, b1);
    pairwise_kernel<<<512, 256>>>(W2, b2, out, write_pairs);
}